// round 16
// baseline (speedup 1.0000x reference)
#include <cuda_runtime.h>
#include <cuda_fp16.h>
#include <math.h>
#include <stdint.h>

// Problem constants
#define M_ROWS   8192
#define N_NODES  255
#define K_DIM    2048
#define N_LEAVES 256
#define N_OUT    100
#define N_PEN    127
#define WPAD     256

// GEMM tiling: CTA 64x256, BK=64, 8 warps of 32x64, grid (128,1)
#define BM 64
#define BN 256
#define BK 64
#define NKCHUNK (K_DIM / BK)         // 32
#define ROWB    144                  // 128 B data + 16 B pad (conflict-free)
#define A_TILE_B (BM * ROWB)         // 9216
#define B_TILE_B (BN * ROWB)         // 36864
#define STAGE_B  (A_TILE_B + B_TILE_B)   // 46080
#define NSTAGE  3
#define SPS      264
#define DYN_BYTES (NSTAGE * STAGE_B)     // 138240

#define NCTA (M_ROWS / BM)           // 128
#define PCAP 32768
#define FLAG_THRESH 0.95f

// ---------------- scratch (device globals) ----------------------------------
__device__ __half g_Wh[WPAD * K_DIM];
__device__ float g_Q[N_LEAVES * N_OUT];
__device__ float g_logQT[N_OUT * N_LEAVES];
__device__ float g_num[N_PEN * NCTA];
__device__ float g_den[N_PEN * NCTA];
__device__ float g_rowloss[NCTA];
__device__ float g_cterm[N_PEN];
__device__ int   g_count;
__device__ int   g_done;
__device__ int   g_pairs[PCAP];
__device__ int   g_rowpend[M_ROWS];
__device__ unsigned long long g_rowbest[M_ROWS];

// ---------------- helpers ----------------------------------------------------
__device__ __forceinline__ uint32_t smem_u32(const void* p) {
    uint32_t a;
    asm("{ .reg .u64 t; cvta.to.shared.u64 t, %1; cvt.u32.u64 %0, t; }"
        : "=r"(a) : "l"(p));
    return a;
}

__device__ __forceinline__ void mma16816(float* c, const uint32_t* a, const uint32_t* b) {
    asm volatile(
        "mma.sync.aligned.m16n8k16.row.col.f32.f16.f16.f32 "
        "{%0,%1,%2,%3}, {%4,%5,%6,%7}, {%8,%9}, {%0,%1,%2,%3};"
        : "+f"(c[0]), "+f"(c[1]), "+f"(c[2]), "+f"(c[3])
        : "r"(a[0]), "r"(a[1]), "r"(a[2]), "r"(a[3]), "r"(b[0]), "r"(b[1]));
}

#define LDSM_X4(r0, r1, r2, r3, addr) \
    asm volatile("ldmatrix.sync.aligned.m8n8.x4.shared.b16 {%0,%1,%2,%3}, [%4];" \
        : "=r"(r0), "=r"(r1), "=r"(r2), "=r"(r3) : "r"(addr))

#define CP_ASYNC16(dst, src) \
    asm volatile("cp.async.cg.shared.global [%0], [%1], 16;" \
        :: "r"(dst), "l"(src) : "memory")
#define CP_COMMIT()  asm volatile("cp.async.commit_group;" ::: "memory")
#define CP_WAIT(n)   asm volatile("cp.async.wait_group %0;" :: "n"(n) : "memory")

#define STS128_AT(addr, r0, r1, r2, r3) \
    asm volatile("st.shared.v4.b32 [%0], {%1, %2, %3, %4};" \
        :: "r"(addr), "r"(r0), "r"(r1), "r"(r2), "r"(r3) : "memory")

__device__ __forceinline__ void cvt_h8(float4 v0, float4 v1, uint32_t* h) {
    __half2 a = __float22half2_rn(make_float2(v0.x, v0.y));
    __half2 b = __float22half2_rn(make_float2(v0.z, v0.w));
    __half2 c = __float22half2_rn(make_float2(v1.x, v1.y));
    __half2 d = __float22half2_rn(make_float2(v1.z, v1.w));
    h[0] = *(uint32_t*)&a; h[1] = *(uint32_t*)&b;
    h[2] = *(uint32_t*)&c; h[3] = *(uint32_t*)&d;
}

// ---------------- kernel P: W fp32 -> fp16 -----------------------------------
#define WF4 (WPAD * K_DIM / 4)
__global__ __launch_bounds__(256) void convertW_kernel(const float* __restrict__ W)
{
    int wi = blockIdx.x * 256 + threadIdx.x;
    if (wi >= WF4) return;
    int row = wi >> 9;
    float4 v = make_float4(0.f, 0.f, 0.f, 0.f);
    if (row < N_NODES) v = ((const float4*)W)[wi];
    __half2 a = __float22half2_rn(make_float2(v.x, v.y));
    __half2 b = __float22half2_rn(make_float2(v.z, v.w));
    ((uint2*)g_Wh)[wi] = make_uint2(*(uint32_t*)&a, *(uint32_t*)&b);
}

// ---------------- kernel 0: log-softmax + counter resets --------------------
__global__ void softmax_kernel(const float* __restrict__ leaf_params) {
    int l = threadIdx.x;
    if (l == 0) { g_count = 0; g_done = 0; }
    if (l >= N_LEAVES) return;
    const float* row = leaf_params + l * N_OUT;
    float mx = -INFINITY;
    for (int o = 0; o < N_OUT; o++) mx = fmaxf(mx, row[o]);
    float s = 0.f;
    for (int o = 0; o < N_OUT; o++) s += expf(row[o] - mx);
    float lse = mx + logf(s);
    for (int o = 0; o < N_OUT; o++) {
        float lq = row[o] - lse;
        g_Q[l * N_OUT + o]        = expf(lq);
        g_logQT[o * N_LEAVES + l] = lq;
    }
}

// ---------------- kernel A: 1-term fp16 GEMM (BK=64, 3-stage) + fused tree --
__global__ __launch_bounds__(256) void gemm_tree_kernel(
    const float* __restrict__ X,
    const float* __restrict__ bias_g, const float* __restrict__ beta_g,
    const int* __restrict__ labels, float* __restrict__ out_output)
{
    extern __shared__ __align__(16) char dyn[];
    __shared__ float s_beta[BN], s_bias[BN];
    __shared__ float sloss[8];
    __shared__ float snum[N_PEN][8];
    __shared__ float sden[N_PEN][8];

    const int tid  = threadIdx.x;
    const int wid  = tid >> 5;
    const int lane = tid & 31;
    const int m_base = blockIdx.x * BM;

    {
        float bt = 0.f, bs = 0.f;
        if (tid < N_NODES) { bt = beta_g[tid]; bs = bias_g[tid]; }
        s_beta[tid] = bt; s_bias[tid] = bs;
    }

    const uint32_t sbase = smem_u32(dyn);

    // X loader: 64 rows x 64 floats/chunk; thread handles 16 consecutive floats
    const int xrow = tid >> 2;           // 0..63
    const int xc16 = (tid & 3) * 16;     // 0,16,32,48
    const float* Xp = X + (size_t)(m_base + xrow) * K_DIM + xc16;
    const uint32_t a_dst = (uint32_t)(xrow * ROWB + xc16 * 2);

    // B loader: 256 rows x 128 B/chunk = 2048 segs of 16B; 8 per thread
    const int brow = tid >> 2;           // +64 per row-iter
    const int bseg = tid & 3;            // segs bseg and bseg+4
    const __half* Wh = g_Wh + (size_t)brow * K_DIM + bseg * 8;
    const uint32_t b_dst = (uint32_t)(brow * ROWB + bseg * 16);

    // compute mapping: warp grid 2x4, warp tile 32x64
    const int wm = wid & 1;
    const int wn = wid >> 1;
    const int g   = lane >> 2;
    const int tig = lane & 3;

    const uint32_t lm_row   = (uint32_t)(lane & 15);
    const uint32_t lm_khalf = (uint32_t)((lane >> 4) * 16);
    const uint32_t a_base = (uint32_t)((wm * 32 + lm_row) * ROWB) + lm_khalf;
    const uint32_t b_base = (uint32_t)((wn * 64 + lm_row) * ROWB) + lm_khalf;

    float acc[2][8][4];
    #pragma unroll
    for (int mi = 0; mi < 2; mi++)
        #pragma unroll
        for (int ni = 0; ni < 8; ni++)
            #pragma unroll
            for (int r = 0; r < 4; r++) acc[mi][ni][r] = 0.f;

    // prologue: issue B chunks 0,1
    #pragma unroll
    for (int s = 0; s < 2; s++) {
        const uint32_t sb = sbase + s * STAGE_B + A_TILE_B;
        #pragma unroll
        for (int it = 0; it < 4; it++) {
            uint32_t d = b_dst + it * 64 * ROWB;
            size_t soff = (size_t)(it * 64) * K_DIM + s * BK;
            CP_ASYNC16(sb + d,      (const char*)(Wh + soff));
            CP_ASYNC16(sb + d + 64, (const char*)(Wh + soff + 32));
        }
        CP_COMMIT();
    }
    float4 ar[4];
    ar[0] = *(const float4*)(Xp);
    ar[1] = *(const float4*)(Xp + 4);
    ar[2] = *(const float4*)(Xp + 8);
    ar[3] = *(const float4*)(Xp + 12);

    for (int kc = 0; kc < NKCHUNK; kc++) {
        const uint32_t sb = sbase + (uint32_t)(kc % 3) * STAGE_B;
        const uint32_t Ahi = sb, Bhi = sb + A_TILE_B;

        // store A regs (chunk kc) into this stage (32 B per thread)
        {
            uint32_t h0[4], h1[4];
            cvt_h8(ar[0], ar[1], h0);
            cvt_h8(ar[2], ar[3], h1);
            STS128_AT(Ahi + a_dst,      h0[0], h0[1], h0[2], h0[3]);
            STS128_AT(Ahi + a_dst + 16, h1[0], h1[1], h1[2], h1[3]);
        }

        // wait for chunk kc's B (newest group = chunk kc+1 may stay pending)
        CP_WAIT(1);
        __syncthreads();

        // issue B chunk kc+2 (stage (kc+2)%3 readers all passed this barrier)
        if (kc + 2 < NKCHUNK) {
            const uint32_t sn = sbase + (uint32_t)((kc + 2) % 3) * STAGE_B + A_TILE_B;
            const int k0 = (kc + 2) * BK;
            #pragma unroll
            for (int it = 0; it < 4; it++) {
                uint32_t d = b_dst + it * 64 * ROWB;
                size_t soff = (size_t)(it * 64) * K_DIM + k0;
                CP_ASYNC16(sn + d,      (const char*)(Wh + soff));
                CP_ASYNC16(sn + d + 64, (const char*)(Wh + soff + 32));
            }
        }
        CP_COMMIT();   // empty group at tail keeps wait accounting uniform

        // prefetch X regs for chunk kc+1
        if (kc + 1 < NKCHUNK) {
            const int k0 = (kc + 1) * BK;
            ar[0] = *(const float4*)(Xp + k0);
            ar[1] = *(const float4*)(Xp + k0 + 4);
            ar[2] = *(const float4*)(Xp + k0 + 8);
            ar[3] = *(const float4*)(Xp + k0 + 12);
        }

        #pragma unroll
        for (int ks = 0; ks < 4; ks++) {
            const uint32_t kb = ks * 32;
            uint32_t ah[2][4], bh[8][2];
            #pragma unroll
            for (int mi = 0; mi < 2; mi++) {
                uint32_t ao = a_base + mi * 16 * ROWB + kb;
                LDSM_X4(ah[mi][0], ah[mi][1], ah[mi][2], ah[mi][3], Ahi + ao);
            }
            #pragma unroll
            for (int np = 0; np < 4; np++) {
                uint32_t bo = b_base + np * 16 * ROWB + kb;
                uint32_t r0, r1, r2, r3;
                LDSM_X4(r0, r1, r2, r3, Bhi + bo);
                bh[2*np][0] = r0; bh[2*np][1] = r2;
                bh[2*np+1][0] = r1; bh[2*np+1][1] = r3;
            }
            #pragma unroll
            for (int mi = 0; mi < 2; mi++)
                #pragma unroll
                for (int ni = 0; ni < 8; ni++)
                    mma16816(acc[mi][ni], ah[mi], bh[ni]);
        }
    }
    __syncthreads();

    // ---- stage gates into smem (overlay pipeline buffers) ----
    float* sp = (float*)dyn;
    #pragma unroll
    for (int mi = 0; mi < 2; mi++) {
        #pragma unroll
        for (int ni = 0; ni < 8; ni++) {
            int rloc = wm * 32 + mi * 16 + g;
            int cloc = wn * 64 + ni * 8 + 2 * tig;
            float bt0 = s_beta[cloc],     bs0 = s_bias[cloc];
            float bt1 = s_beta[cloc + 1], bs1 = s_bias[cloc + 1];
            float z0 = bt0 * (acc[mi][ni][0] + bs0);
            float z1 = bt1 * (acc[mi][ni][1] + bs1);
            float z2 = bt0 * (acc[mi][ni][2] + bs0);
            float z3 = bt1 * (acc[mi][ni][3] + bs1);
            bool v255 = (cloc + 1 == 255);
            sp[rloc * SPS + cloc]           = 1.f / (1.f + expf(-z0));
            sp[rloc * SPS + cloc + 1]       = v255 ? 0.f : 1.f / (1.f + expf(-z1));
            sp[(rloc + 8) * SPS + cloc]     = 1.f / (1.f + expf(-z2));
            sp[(rloc + 8) * SPS + cloc + 1] = v255 ? 0.f : 1.f / (1.f + expf(-z3));
        }
    }
    __syncthreads();

    // ---- fused tree ----
    float nacc[4] = {0.f, 0.f, 0.f, 0.f};
    float dacc[4] = {0.f, 0.f, 0.f, 0.f};
    float lossacc = 0.f;

    for (int r = 0; r < 8; r++) {
        const int lr = wid * 8 + r;
        const int i  = m_base + lr;
        const float* spw = sp + lr * SPS;
        const int label = labels[i];

        unsigned m = 32u + (unsigned)lane;
        float path5 = 1.f;
        #pragma unroll
        for (int k = 4; k >= 0; --k) {
            unsigned a = m >> (k + 1);
            float pa = spw[a - 1];
            path5 *= ((m >> k) & 1u) ? pa : (1.f - pa);
        }
        float p_m = spw[m - 1];

        const float4* lqp = (const float4*)(g_logQT + label * N_LEAVES + lane * 8);
        float4 q0 = lqp[0], q1 = lqp[1];
        float lqv[8] = {q0.x, q0.y, q0.z, q0.w, q1.x, q1.y, q1.z, q1.w};

        float lps[8];
        float best = -1.f;
        int besti = 0;
        #pragma unroll
        for (int b1 = 0; b1 < 2; b1++) {
            unsigned n6 = 2u * m + b1;
            float p6 = path5 * (b1 ? p_m : (1.f - p_m));
            float g6 = spw[n6 - 1];
            #pragma unroll
            for (int b2 = 0; b2 < 2; b2++) {
                unsigned n7 = 2u * n6 + b2;
                float p7 = p6 * (b2 ? g6 : (1.f - g6));
                float g7 = spw[n7 - 1];
                #pragma unroll
                for (int b3 = 0; b3 < 2; b3++) {
                    int rr = b1 * 4 + b2 * 2 + b3;
                    float lp = p7 * (b3 ? g7 : (1.f - g7));
                    lps[rr] = lp;
                    lossacc += lp * lqv[rr];
                    if (lp > best) { best = lp; besti = lane * 8 + rr; }
                }
            }
        }

        #pragma unroll
        for (int o = 16; o > 0; o >>= 1) {
            float ob = __shfl_xor_sync(0xFFFFFFFFu, best, o);
            int   oi = __shfl_xor_sync(0xFFFFFFFFu, besti, o);
            if (ob > best || (ob == best && oi < besti)) { best = ob; besti = oi; }
        }

        const float* qrow = g_Q + besti * N_OUT;
        for (int o = lane; o < N_OUT; o += 32)
            out_output[(size_t)i * N_OUT + o] = qrow[o];

        // ---- candidate emission ----
        {
            float thr = FLAG_THRESH * best;
            unsigned cm = 0;
            #pragma unroll
            for (int rr = 0; rr < 8; rr++)
                if (lps[rr] >= thr) cm |= (1u << rr);
            int myc = __popc(cm);
            int scan = myc;
            #pragma unroll
            for (int o = 1; o < 32; o <<= 1) {
                int v = __shfl_up_sync(0xFFFFFFFFu, scan, o);
                if (lane >= o) scan += v;
            }
            int total = __shfl_sync(0xFFFFFFFFu, scan, 31);
            int excl  = scan - myc;
            if (total > 1) {
                int base = 0;
                if (lane == 0) {
                    base = atomicAdd(&g_count, total);
                    g_rowbest[i] = 0ULL;
                    g_rowpend[i] = total;
                }
                base = __shfl_sync(0xFFFFFFFFu, base, 0);
                if (base + total <= PCAP) {
                    int off = base + excl;
                    #pragma unroll
                    for (int rr = 0; rr < 8; rr++)
                        if (cm & (1u << rr))
                            g_pairs[off++] = (i << 8) | (lane * 8 + rr);
                }
            }
        }

        #pragma unroll
        for (int j = 0; j < 4; j++) {
            int t = j * 32 + lane;
            if (t < N_PEN) {
                unsigned m2 = (unsigned)t + 1u;
                int nb = 31 - __clz((int)m2);
                float iv = 1.f;
                for (int k = nb - 1; k >= 0; --k) {
                    unsigned a = m2 >> (k + 1);
                    float pa = spw[a - 1];
                    iv *= ((m2 >> k) & 1u) ? pa : (1.f - pa);
                }
                nacc[j] += spw[t] * iv;
                dacc[j] += iv;
            }
        }
    }

    #pragma unroll
    for (int o = 16; o > 0; o >>= 1)
        lossacc += __shfl_xor_sync(0xFFFFFFFFu, lossacc, o);
    if (lane == 0) sloss[wid] = lossacc;

    #pragma unroll
    for (int j = 0; j < 4; j++) {
        int t = j * 32 + lane;
        if (t < N_PEN) { snum[t][wid] = nacc[j]; sden[t][wid] = dacc[j]; }
    }
    __syncthreads();

    for (int t = tid; t < N_PEN; t += 256) {
        float sn = 0.f, sd = 0.f;
        #pragma unroll
        for (int r = 0; r < 8; r++) { sn += snum[t][r]; sd += sden[t][r]; }
        g_num[t * NCTA + blockIdx.x] = sn;
        g_den[t * NCTA + blockIdx.x] = sd;
    }
    if (tid == 0) {
        float s = 0.f;
        #pragma unroll
        for (int r = 0; r < 8; r++) s += sloss[r];
        g_rowloss[blockIdx.x] = s;
    }
}

// ---------------- kernel R1: exact score per pair + inline fixup ------------
__global__ __launch_bounds__(256) void pairscore_kernel(
    const float* __restrict__ X, const float* __restrict__ W,
    const float* __restrict__ bias_g, const float* __restrict__ beta_g,
    float* __restrict__ out_output)
{
    int cnt = g_count; if (cnt > PCAP) cnt = PCAP;
    const int pidx = blockIdx.x * 8 + (threadIdx.x >> 5);
    const int lane = threadIdx.x & 31;
    if (pidx >= cnt) return;

    const int pair = g_pairs[pidx];
    const int row  = pair >> 8;
    const int leaf = pair & 255;
    const unsigned m = 256u + (unsigned)leaf;

    int nodes[8];
    #pragma unroll
    for (int k = 0; k < 8; k++) nodes[k] = (int)(m >> (k + 1)) - 1;

    const float4* xr = (const float4*)(X + (size_t)row * K_DIM);
    float acc[8] = {0.f,0.f,0.f,0.f,0.f,0.f,0.f,0.f};

    #pragma unroll 2
    for (int it = lane; it < K_DIM / 4; it += 32) {
        float4 xv = xr[it];
        #pragma unroll
        for (int k = 0; k < 8; k++) {
            float4 wv = ((const float4*)(W + (size_t)nodes[k] * K_DIM))[it];
            acc[k] += wv.x*xv.x + wv.y*xv.y + wv.z*xv.z + wv.w*xv.w;
        }
    }
    #pragma unroll
    for (int k = 0; k < 8; k++)
        #pragma unroll
        for (int o = 16; o > 0; o >>= 1)
            acc[k] += __shfl_xor_sync(0xFFFFFFFFu, acc[k], o);

    int last = 0;
    unsigned long long winner = 0ULL;
    if (lane == 0) {
        float prod = 1.f;
        #pragma unroll
        for (int k = 7; k >= 0; k--) {
            int n = nodes[k];
            float z = beta_g[n] * (acc[k] + bias_g[n]);
            float p = 1.f / (1.f + expf(-z));
            prod *= ((m >> k) & 1u) ? p : (1.f - p);
        }
        unsigned u = __float_as_uint(prod);
        unsigned mono = (u & 0x80000000u) ? ~u : (u | 0x80000000u);
        unsigned long long packed =
            ((unsigned long long)mono << 32) | (unsigned)(255 - leaf);
        atomicMax(&g_rowbest[row], packed);
        __threadfence();
        if (atomicSub(&g_rowpend[row], 1) == 1) {
            last = 1;
            winner = atomicAdd(&g_rowbest[row], 0ULL);
        }
    }
    last = __shfl_sync(0xFFFFFFFFu, last, 0);
    if (last) {
        unsigned lo = __shfl_sync(0xFFFFFFFFu, (unsigned)(winner & 0xFFu), 0);
        int wleaf = 255 - (int)lo;
        const float* qrow = g_Q + wleaf * N_OUT;
        for (int o = lane; o < N_OUT; o += 32)
            out_output[(size_t)row * N_OUT + o] = qrow[o];
    }
}

// ---------------- kernel C: reductions + fused final C ----------------------
__global__ __launch_bounds__(128) void reduce_kernel(float* __restrict__ out)
{
    const int j = blockIdx.x;
    const int t = threadIdx.x;
    __shared__ float s1[128];
    __shared__ float s2[128];
    __shared__ int s_last;

    if (j < N_PEN) {
        s1[t] = g_num[j * NCTA + t];
        s2[t] = g_den[j * NCTA + t];
        __syncthreads();
        #pragma unroll
        for (int s = 64; s > 0; s >>= 1) {
            if (t < s) { s1[t] += s1[t + s]; s2[t] += s2[t + s]; }
            __syncthreads();
        }
        if (t == 0) {
            float alpha = s1[0] / s2[0];
            int depth = 32 - __clz(j + 1);
            float lm = 0.1f * exp2f(-(float)depth);
            g_cterm[j] = lm * 0.5f * (logf(alpha) + log1pf(-alpha));
        }
    } else {
        s1[t] = g_rowloss[t];
        __syncthreads();
        #pragma unroll
        for (int s = 64; s > 0; s >>= 1) {
            if (t < s) s1[t] += s1[t + s];
            __syncthreads();
        }
        if (t == 0) out[0] = -(s1[0] / (float)M_ROWS);
    }

    __threadfence();
    __syncthreads();
    if (t == 0) {
        int d = atomicAdd(&g_done, 1);
        s_last = (d == N_PEN);
    }
    __syncthreads();
    if (s_last) {
        __threadfence();
        s1[t] = (t < N_PEN) ? g_cterm[t] : 0.f;
        __syncthreads();
        #pragma unroll
        for (int s = 64; s > 0; s >>= 1) {
            if (t < s) s1[t] += s1[t + s];
            __syncthreads();
        }
        if (t == 0) out[1 + M_ROWS * N_OUT] = -s1[0];
    }
}

// ---------------- entry -----------------------------------------------------
extern "C" void kernel_launch(void* const* d_in, const int* in_sizes, int n_in,
                              void* d_out, int out_size)
{
    const float* x           = (const float*)d_in[0];
    const int*   labels      = (const int*)  d_in[1];
    const float* W           = (const float*)d_in[2];
    const float* b           = (const float*)d_in[3];
    const float* beta        = (const float*)d_in[4];
    const float* leaf_params = (const float*)d_in[5];
    float* out = (float*)d_out;

    cudaFuncSetAttribute(gemm_tree_kernel,
                         cudaFuncAttributeMaxDynamicSharedMemorySize, DYN_BYTES);

    convertW_kernel<<<(WF4 + 255) / 256, 256>>>(W);
    softmax_kernel<<<1, 256>>>(leaf_params);
    gemm_tree_kernel<<<NCTA, 256, DYN_BYTES>>>(x, b, beta, labels, out + 1);
    pairscore_kernel<<<PCAP / 8, 256>>>(x, W, b, beta, out + 1);
    reduce_kernel<<<N_PEN + 1, 128>>>(out);
}

// round 17
// speedup vs baseline: 1.3286x; 1.3286x over previous
#include <cuda_runtime.h>
#include <cuda_fp16.h>
#include <math.h>
#include <stdint.h>

// Problem constants
#define M_ROWS   8192
#define N_NODES  255
#define K_DIM    2048
#define N_LEAVES 256
#define N_OUT    100
#define N_PEN    127
#define WPAD     256

// GEMM tiling: CTA 64x256, BK=32, 8 warps of 32x64, grid (128,1)  [R15 config]
#define BM 64
#define BN 256
#define BK 32
#define NKCHUNK (K_DIM / BK)         // 64
#define ROWB    80
#define A_TILE_B (BM * ROWB)         // 5120
#define B_TILE_B (BN * ROWB)         // 20480
#define STAGE_B  (A_TILE_B + B_TILE_B)   // 25600
#define NSTAGE  4
#define SPS      264
#define DYN_BYTES (NSTAGE * STAGE_B)     // 102400

#define NCTA (M_ROWS / BM)           // 128
#define PCAP 32768
#define FLAG_THRESH 0.95f

// ---------------- scratch (device globals) ----------------------------------
__device__ __half g_Wh[WPAD * K_DIM];
__device__ float g_Q[N_LEAVES * N_OUT];
__device__ float g_logQT[N_OUT * N_LEAVES];
__device__ float g_num[N_PEN * NCTA];
__device__ float g_den[N_PEN * NCTA];
__device__ float g_rowloss[NCTA];
__device__ float g_cterm[N_PEN];
__device__ int   g_count;
__device__ int   g_done;
__device__ int   g_pairs[PCAP];
__device__ int   g_rowpend[M_ROWS];
__device__ unsigned long long g_rowbest[M_ROWS];

// ---------------- helpers ----------------------------------------------------
__device__ __forceinline__ uint32_t smem_u32(const void* p) {
    uint32_t a;
    asm("{ .reg .u64 t; cvta.to.shared.u64 t, %1; cvt.u32.u64 %0, t; }"
        : "=r"(a) : "l"(p));
    return a;
}

__device__ __forceinline__ void mma16816(float* c, const uint32_t* a, const uint32_t* b) {
    asm volatile(
        "mma.sync.aligned.m16n8k16.row.col.f32.f16.f16.f32 "
        "{%0,%1,%2,%3}, {%4,%5,%6,%7}, {%8,%9}, {%0,%1,%2,%3};"
        : "+f"(c[0]), "+f"(c[1]), "+f"(c[2]), "+f"(c[3])
        : "r"(a[0]), "r"(a[1]), "r"(a[2]), "r"(a[3]), "r"(b[0]), "r"(b[1]));
}

#define LDSM_X4(r0, r1, r2, r3, addr) \
    asm volatile("ldmatrix.sync.aligned.m8n8.x4.shared.b16 {%0,%1,%2,%3}, [%4];" \
        : "=r"(r0), "=r"(r1), "=r"(r2), "=r"(r3) : "r"(addr))

#define CP_ASYNC16(dst, src) \
    asm volatile("cp.async.cg.shared.global [%0], [%1], 16;" \
        :: "r"(dst), "l"(src) : "memory")
#define CP_COMMIT()  asm volatile("cp.async.commit_group;" ::: "memory")
#define CP_WAIT(n)   asm volatile("cp.async.wait_group %0;" :: "n"(n) : "memory")

#define STS128_AT(addr, r0, r1, r2, r3) \
    asm volatile("st.shared.v4.b32 [%0], {%1, %2, %3, %4};" \
        :: "r"(addr), "r"(r0), "r"(r1), "r"(r2), "r"(r3) : "memory")

__device__ __forceinline__ void cvt_h8(float4 v0, float4 v1, uint32_t* h) {
    __half2 a = __float22half2_rn(make_float2(v0.x, v0.y));
    __half2 b = __float22half2_rn(make_float2(v0.z, v0.w));
    __half2 c = __float22half2_rn(make_float2(v1.x, v1.y));
    __half2 d = __float22half2_rn(make_float2(v1.z, v1.w));
    h[0] = *(uint32_t*)&a; h[1] = *(uint32_t*)&b;
    h[2] = *(uint32_t*)&c; h[3] = *(uint32_t*)&d;
}

// ---------------- kernel P: W fp32 -> fp16 (+ counter reset) -----------------
#define WF4 (WPAD * K_DIM / 4)
__global__ __launch_bounds__(256) void convertW_kernel(const float* __restrict__ W)
{
    if (blockIdx.x == 0 && threadIdx.x == 0) { g_count = 0; g_done = 0; }
    int wi = blockIdx.x * 256 + threadIdx.x;
    if (wi >= WF4) return;
    int row = wi >> 9;
    float4 v = make_float4(0.f, 0.f, 0.f, 0.f);
    if (row < N_NODES) v = ((const float4*)W)[wi];
    __half2 a = __float22half2_rn(make_float2(v.x, v.y));
    __half2 b = __float22half2_rn(make_float2(v.z, v.w));
    ((uint2*)g_Wh)[wi] = make_uint2(*(uint32_t*)&a, *(uint32_t*)&b);
}

// ---------------- kernel 0: parallel log-softmax (warp per leaf) ------------
__global__ __launch_bounds__(256) void softmax_kernel(const float* __restrict__ leaf_params) {
    const int l    = blockIdx.x * 8 + (threadIdx.x >> 5);   // leaf 0..255
    const int lane = threadIdx.x & 31;
    const float* row = leaf_params + l * N_OUT;

    // load 4 strided values per lane (100 < 128)
    float v[4];
    #pragma unroll
    for (int j = 0; j < 4; j++) {
        int o = lane + j * 32;
        v[j] = (o < N_OUT) ? row[o] : -INFINITY;
    }
    float mx = fmaxf(fmaxf(v[0], v[1]), fmaxf(v[2], v[3]));
    #pragma unroll
    for (int o = 16; o > 0; o >>= 1)
        mx = fmaxf(mx, __shfl_xor_sync(0xFFFFFFFFu, mx, o));

    float s = 0.f;
    #pragma unroll
    for (int j = 0; j < 4; j++) {
        int o = lane + j * 32;
        if (o < N_OUT) s += expf(v[j] - mx);
    }
    #pragma unroll
    for (int o = 16; o > 0; o >>= 1)
        s += __shfl_xor_sync(0xFFFFFFFFu, s, o);
    float lse = mx + logf(s);

    #pragma unroll
    for (int j = 0; j < 4; j++) {
        int o = lane + j * 32;
        if (o < N_OUT) {
            float lq = v[j] - lse;
            g_Q[l * N_OUT + o]        = expf(lq);
            g_logQT[o * N_LEAVES + l] = lq;
        }
    }
}

// ---------------- kernel A: 1-term fp16 GEMM (4-stage pipe) + fused tree ----
__global__ __launch_bounds__(256) void gemm_tree_kernel(
    const float* __restrict__ X,
    const float* __restrict__ bias_g, const float* __restrict__ beta_g,
    const int* __restrict__ labels, float* __restrict__ out_output)
{
    extern __shared__ __align__(16) char dyn[];
    __shared__ float s_beta[BN], s_bias[BN];
    __shared__ float sloss[8];
    __shared__ float snum[N_PEN][8];
    __shared__ float sden[N_PEN][8];

    const int tid  = threadIdx.x;
    const int wid  = tid >> 5;
    const int lane = tid & 31;
    const int m_base = blockIdx.x * BM;

    {
        float bt = 0.f, bs = 0.f;
        if (tid < N_NODES) { bt = beta_g[tid]; bs = bias_g[tid]; }
        s_beta[tid] = bt; s_bias[tid] = bs;
    }

    const uint32_t sbase = smem_u32(dyn);

    const int xrow = tid >> 2;
    const int xc8  = (tid & 3) * 8;
    const float* Xp = X + (size_t)(m_base + xrow) * K_DIM + xc8;
    const uint32_t a_dst = (uint32_t)(xrow * ROWB + xc8 * 2);

    const int brow = tid >> 2;
    const int bc16 = tid & 3;
    const __half* Wh = g_Wh + (size_t)brow * K_DIM + bc16 * 8;
    const uint32_t b_dst = (uint32_t)(brow * ROWB + bc16 * 16);

    const int wm = wid & 1;
    const int wn = wid >> 1;
    const int g   = lane >> 2;
    const int tig = lane & 3;

    const uint32_t lm_row   = (uint32_t)(lane & 15);
    const uint32_t lm_khalf = (uint32_t)((lane >> 4) * 16);
    const uint32_t a_base = (uint32_t)((wm * 32 + lm_row) * ROWB) + lm_khalf;
    const uint32_t b_base = (uint32_t)((wn * 64 + lm_row) * ROWB) + lm_khalf;

    float acc[2][8][4];
    #pragma unroll
    for (int mi = 0; mi < 2; mi++)
        #pragma unroll
        for (int ni = 0; ni < 8; ni++)
            #pragma unroll
            for (int r = 0; r < 4; r++) acc[mi][ni][r] = 0.f;

    #pragma unroll
    for (int s = 0; s < 3; s++) {
        const uint32_t sb = sbase + s * STAGE_B + A_TILE_B;
        #pragma unroll
        for (int it = 0; it < 4; it++)
            CP_ASYNC16(sb + b_dst + it * 64 * ROWB,
                       (const char*)(Wh + (size_t)(it * 64) * K_DIM + s * BK));
        CP_COMMIT();
    }
    float4 areg0 = *(const float4*)(Xp);
    float4 areg1 = *(const float4*)(Xp + 4);

    for (int kc = 0; kc < NKCHUNK; kc++) {
        const uint32_t sb = sbase + (uint32_t)(kc & 3) * STAGE_B;
        const uint32_t Ahi = sb, Bhi = sb + A_TILE_B;

        {
            uint32_t h[4];
            cvt_h8(areg0, areg1, h);
            STS128_AT(Ahi + a_dst, h[0], h[1], h[2], h[3]);
        }

        CP_WAIT(2);
        __syncthreads();

        if (kc + 3 < NKCHUNK) {
            const uint32_t sn = sbase + (uint32_t)((kc + 3) & 3) * STAGE_B + A_TILE_B;
            const int k0 = (kc + 3) * BK;
            #pragma unroll
            for (int it = 0; it < 4; it++)
                CP_ASYNC16(sn + b_dst + it * 64 * ROWB,
                           (const char*)(Wh + (size_t)(it * 64) * K_DIM + k0));
        }
        CP_COMMIT();

        if (kc + 1 < NKCHUNK) {
            const int k0 = (kc + 1) * BK;
            areg0 = *(const float4*)(Xp + k0);
            areg1 = *(const float4*)(Xp + k0 + 4);
        }

        #pragma unroll
        for (int ks = 0; ks < 2; ks++) {
            const uint32_t kb = ks * 32;
            uint32_t ah[2][4], bh[8][2];
            #pragma unroll
            for (int mi = 0; mi < 2; mi++) {
                uint32_t ao = a_base + mi * 16 * ROWB + kb;
                LDSM_X4(ah[mi][0], ah[mi][1], ah[mi][2], ah[mi][3], Ahi + ao);
            }
            #pragma unroll
            for (int np = 0; np < 4; np++) {
                uint32_t bo = b_base + np * 16 * ROWB + kb;
                uint32_t r0, r1, r2, r3;
                LDSM_X4(r0, r1, r2, r3, Bhi + bo);
                bh[2*np][0] = r0; bh[2*np][1] = r2;
                bh[2*np+1][0] = r1; bh[2*np+1][1] = r3;
            }
            #pragma unroll
            for (int mi = 0; mi < 2; mi++)
                #pragma unroll
                for (int ni = 0; ni < 8; ni++)
                    mma16816(acc[mi][ni], ah[mi], bh[ni]);
        }
    }
    __syncthreads();

    // ---- stage gates into smem (overlay pipeline buffers) ----
    float* sp = (float*)dyn;
    #pragma unroll
    for (int mi = 0; mi < 2; mi++) {
        #pragma unroll
        for (int ni = 0; ni < 8; ni++) {
            int rloc = wm * 32 + mi * 16 + g;
            int cloc = wn * 64 + ni * 8 + 2 * tig;
            float bt0 = s_beta[cloc],     bs0 = s_bias[cloc];
            float bt1 = s_beta[cloc + 1], bs1 = s_bias[cloc + 1];
            float z0 = bt0 * (acc[mi][ni][0] + bs0);
            float z1 = bt1 * (acc[mi][ni][1] + bs1);
            float z2 = bt0 * (acc[mi][ni][2] + bs0);
            float z3 = bt1 * (acc[mi][ni][3] + bs1);
            bool v255 = (cloc + 1 == 255);
            sp[rloc * SPS + cloc]           = 1.f / (1.f + expf(-z0));
            sp[rloc * SPS + cloc + 1]       = v255 ? 0.f : 1.f / (1.f + expf(-z1));
            sp[(rloc + 8) * SPS + cloc]     = 1.f / (1.f + expf(-z2));
            sp[(rloc + 8) * SPS + cloc + 1] = v255 ? 0.f : 1.f / (1.f + expf(-z3));
        }
    }
    __syncthreads();

    // ---- fused tree ----
    float nacc[4] = {0.f, 0.f, 0.f, 0.f};
    float dacc[4] = {0.f, 0.f, 0.f, 0.f};
    float lossacc = 0.f;

    for (int r = 0; r < 8; r++) {
        const int lr = wid * 8 + r;
        const int i  = m_base + lr;
        const float* spw = sp + lr * SPS;
        const int label = labels[i];

        unsigned m = 32u + (unsigned)lane;
        float path5 = 1.f;
        #pragma unroll
        for (int k = 4; k >= 0; --k) {
            unsigned a = m >> (k + 1);
            float pa = spw[a - 1];
            path5 *= ((m >> k) & 1u) ? pa : (1.f - pa);
        }
        float p_m = spw[m - 1];

        const float4* lqp = (const float4*)(g_logQT + label * N_LEAVES + lane * 8);
        float4 q0 = lqp[0], q1 = lqp[1];
        float lqv[8] = {q0.x, q0.y, q0.z, q0.w, q1.x, q1.y, q1.z, q1.w};

        float lps[8];
        float best = -1.f;
        int besti = 0;
        #pragma unroll
        for (int b1 = 0; b1 < 2; b1++) {
            unsigned n6 = 2u * m + b1;
            float p6 = path5 * (b1 ? p_m : (1.f - p_m));
            float g6 = spw[n6 - 1];
            #pragma unroll
            for (int b2 = 0; b2 < 2; b2++) {
                unsigned n7 = 2u * n6 + b2;
                float p7 = p6 * (b2 ? g6 : (1.f - g6));
                float g7 = spw[n7 - 1];
                #pragma unroll
                for (int b3 = 0; b3 < 2; b3++) {
                    int rr = b1 * 4 + b2 * 2 + b3;
                    float lp = p7 * (b3 ? g7 : (1.f - g7));
                    lps[rr] = lp;
                    lossacc += lp * lqv[rr];
                    if (lp > best) { best = lp; besti = lane * 8 + rr; }
                }
            }
        }

        #pragma unroll
        for (int o = 16; o > 0; o >>= 1) {
            float ob = __shfl_xor_sync(0xFFFFFFFFu, best, o);
            int   oi = __shfl_xor_sync(0xFFFFFFFFu, besti, o);
            if (ob > best || (ob == best && oi < besti)) { best = ob; besti = oi; }
        }

        const float* qrow = g_Q + besti * N_OUT;
        for (int o = lane; o < N_OUT; o += 32)
            out_output[(size_t)i * N_OUT + o] = qrow[o];

        // ---- candidate emission ----
        {
            float thr = FLAG_THRESH * best;
            unsigned cm = 0;
            #pragma unroll
            for (int rr = 0; rr < 8; rr++)
                if (lps[rr] >= thr) cm |= (1u << rr);
            int myc = __popc(cm);
            int scan = myc;
            #pragma unroll
            for (int o = 1; o < 32; o <<= 1) {
                int v = __shfl_up_sync(0xFFFFFFFFu, scan, o);
                if (lane >= o) scan += v;
            }
            int total = __shfl_sync(0xFFFFFFFFu, scan, 31);
            int excl  = scan - myc;
            if (total > 1) {
                int base = 0;
                if (lane == 0) {
                    base = atomicAdd(&g_count, total);
                    g_rowbest[i] = 0ULL;
                    g_rowpend[i] = total;
                }
                base = __shfl_sync(0xFFFFFFFFu, base, 0);
                if (base + total <= PCAP) {
                    int off = base + excl;
                    #pragma unroll
                    for (int rr = 0; rr < 8; rr++)
                        if (cm & (1u << rr))
                            g_pairs[off++] = (i << 8) | (lane * 8 + rr);
                }
            }
        }

        #pragma unroll
        for (int j = 0; j < 4; j++) {
            int t = j * 32 + lane;
            if (t < N_PEN) {
                unsigned m2 = (unsigned)t + 1u;
                int nb = 31 - __clz((int)m2);
                float iv = 1.f;
                for (int k = nb - 1; k >= 0; --k) {
                    unsigned a = m2 >> (k + 1);
                    float pa = spw[a - 1];
                    iv *= ((m2 >> k) & 1u) ? pa : (1.f - pa);
                }
                nacc[j] += spw[t] * iv;
                dacc[j] += iv;
            }
        }
    }

    #pragma unroll
    for (int o = 16; o > 0; o >>= 1)
        lossacc += __shfl_xor_sync(0xFFFFFFFFu, lossacc, o);
    if (lane == 0) sloss[wid] = lossacc;

    #pragma unroll
    for (int j = 0; j < 4; j++) {
        int t = j * 32 + lane;
        if (t < N_PEN) { snum[t][wid] = nacc[j]; sden[t][wid] = dacc[j]; }
    }
    __syncthreads();

    for (int t = tid; t < N_PEN; t += 256) {
        float sn = 0.f, sd = 0.f;
        #pragma unroll
        for (int r = 0; r < 8; r++) { sn += snum[t][r]; sd += sden[t][r]; }
        g_num[t * NCTA + blockIdx.x] = sn;
        g_den[t * NCTA + blockIdx.x] = sd;
    }
    if (tid == 0) {
        float s = 0.f;
        #pragma unroll
        for (int r = 0; r < 8; r++) s += sloss[r];
        g_rowloss[blockIdx.x] = s;
    }
}

// ---------------- kernel R1: exact score per pair + inline fixup ------------
__global__ __launch_bounds__(256) void pairscore_kernel(
    const float* __restrict__ X, const float* __restrict__ W,
    const float* __restrict__ bias_g, const float* __restrict__ beta_g,
    float* __restrict__ out_output)
{
    int cnt = g_count; if (cnt > PCAP) cnt = PCAP;
    const int pidx = blockIdx.x * 8 + (threadIdx.x >> 5);
    const int lane = threadIdx.x & 31;
    if (pidx >= cnt) return;

    const int pair = g_pairs[pidx];
    const int row  = pair >> 8;
    const int leaf = pair & 255;
    const unsigned m = 256u + (unsigned)leaf;

    int nodes[8];
    #pragma unroll
    for (int k = 0; k < 8; k++) nodes[k] = (int)(m >> (k + 1)) - 1;

    const float4* xr = (const float4*)(X + (size_t)row * K_DIM);
    float acc[8] = {0.f,0.f,0.f,0.f,0.f,0.f,0.f,0.f};

    #pragma unroll 4
    for (int it = lane; it < K_DIM / 4; it += 32) {
        float4 xv = xr[it];
        #pragma unroll
        for (int k = 0; k < 8; k++) {
            float4 wv = ((const float4*)(W + (size_t)nodes[k] * K_DIM))[it];
            acc[k] += wv.x*xv.x + wv.y*xv.y + wv.z*xv.z + wv.w*xv.w;
        }
    }
    #pragma unroll
    for (int k = 0; k < 8; k++)
        #pragma unroll
        for (int o = 16; o > 0; o >>= 1)
            acc[k] += __shfl_xor_sync(0xFFFFFFFFu, acc[k], o);

    int last = 0;
    unsigned long long winner = 0ULL;
    if (lane == 0) {
        float prod = 1.f;
        #pragma unroll
        for (int k = 7; k >= 0; k--) {
            int n = nodes[k];
            float z = beta_g[n] * (acc[k] + bias_g[n]);
            float p = 1.f / (1.f + expf(-z));
            prod *= ((m >> k) & 1u) ? p : (1.f - p);
        }
        unsigned u = __float_as_uint(prod);
        unsigned mono = (u & 0x80000000u) ? ~u : (u | 0x80000000u);
        unsigned long long packed =
            ((unsigned long long)mono << 32) | (unsigned)(255 - leaf);
        atomicMax(&g_rowbest[row], packed);
        __threadfence();
        if (atomicSub(&g_rowpend[row], 1) == 1) {
            last = 1;
            winner = atomicAdd(&g_rowbest[row], 0ULL);
        }
    }
    last = __shfl_sync(0xFFFFFFFFu, last, 0);
    if (last) {
        unsigned lo = __shfl_sync(0xFFFFFFFFu, (unsigned)(winner & 0xFFu), 0);
        int wleaf = 255 - (int)lo;
        const float* qrow = g_Q + wleaf * N_OUT;
        for (int o = lane; o < N_OUT; o += 32)
            out_output[(size_t)row * N_OUT + o] = qrow[o];
    }
}

// ---------------- kernel C: reductions + fused final C ----------------------
__global__ __launch_bounds__(128) void reduce_kernel(float* __restrict__ out)
{
    const int j = blockIdx.x;
    const int t = threadIdx.x;
    __shared__ float s1[128];
    __shared__ float s2[128];
    __shared__ int s_last;

    if (j < N_PEN) {
        s1[t] = g_num[j * NCTA + t];
        s2[t] = g_den[j * NCTA + t];
        __syncthreads();
        #pragma unroll
        for (int s = 64; s > 0; s >>= 1) {
            if (t < s) { s1[t] += s1[t + s]; s2[t] += s2[t + s]; }
            __syncthreads();
        }
        if (t == 0) {
            float alpha = s1[0] / s2[0];
            int depth = 32 - __clz(j + 1);
            float lm = 0.1f * exp2f(-(float)depth);
            g_cterm[j] = lm * 0.5f * (logf(alpha) + log1pf(-alpha));
        }
    } else {
        s1[t] = g_rowloss[t];
        __syncthreads();
        #pragma unroll
        for (int s = 64; s > 0; s >>= 1) {
            if (t < s) s1[t] += s1[t + s];
            __syncthreads();
        }
        if (t == 0) out[0] = -(s1[0] / (float)M_ROWS);
    }

    __threadfence();
    __syncthreads();
    if (t == 0) {
        int d = atomicAdd(&g_done, 1);
        s_last = (d == N_PEN);
    }
    __syncthreads();
    if (s_last) {
        __threadfence();
        s1[t] = (t < N_PEN) ? g_cterm[t] : 0.f;
        __syncthreads();
        #pragma unroll
        for (int s = 64; s > 0; s >>= 1) {
            if (t < s) s1[t] += s1[t + s];
            __syncthreads();
        }
        if (t == 0) out[1 + M_ROWS * N_OUT] = -s1[0];
    }
}

// ---------------- entry -----------------------------------------------------
extern "C" void kernel_launch(void* const* d_in, const int* in_sizes, int n_in,
                              void* d_out, int out_size)
{
    const float* x           = (const float*)d_in[0];
    const int*   labels      = (const int*)  d_in[1];
    const float* W           = (const float*)d_in[2];
    const float* b           = (const float*)d_in[3];
    const float* beta        = (const float*)d_in[4];
    const float* leaf_params = (const float*)d_in[5];
    float* out = (float*)d_out;

    cudaFuncSetAttribute(gemm_tree_kernel,
                         cudaFuncAttributeMaxDynamicSharedMemorySize, DYN_BYTES);

    convertW_kernel<<<(WF4 + 255) / 256, 256>>>(W);
    softmax_kernel<<<32, 256>>>(leaf_params);
    gemm_tree_kernel<<<NCTA, 256, DYN_BYTES>>>(x, b, beta, labels, out + 1);
    pairscore_kernel<<<PCAP / 8, 256>>>(x, W, b, beta, out + 1);
    reduce_kernel<<<N_PEN + 1, 128>>>(out);
}